// round 16
// baseline (speedup 1.0000x reference)
#include <cuda_runtime.h>
#include <cuda_fp16.h>
#include <cstdint>

// out = softmax(normalize(Q)@normalize(K)^T) @ K,  N=65536, K=4096, D=128, fp32
// fp16 mma.sync dataflow, split-K x4 (proven, rel_err 1.1e-4).
// R15: combine kernel FUSED into mb_main via per-qtile arrival counter
//      (threadFenceReduction pattern) — combine overlaps compute, one less
//      launch, no serialized 160MB pass at the end.

#define NQ 65536
#define NKEY 4096
#define DIM 128
#define BM 128            // 4 warps x 32 rows
#define BK 64
#define NSPLIT 4
#define TPS (NKEY / BK / NSPLIT)   // 16 tiles per split
#define NQT (NQ / BM)              // 512 q-tiles
#define NTHREADS 128
#define SROWK 272
#define SROWV 144

__device__ __align__(16) __half g_Qh[(size_t)NQ * DIM];    // normalized Q * log2e
__device__ __align__(16) __half g_Kh[(size_t)NKEY * DIM];  // NORMALIZED keys
__device__ __align__(16) __half g_Vt[(size_t)DIM * NKEY];  // raw keys^T [d][key]
__device__ __align__(16) float  g_colsum[DIM];
__device__ __align__(16) __half g_OpH[NSPLIT][(size_t)NQ * DIM];  // fp16 partials
__device__ __align__(16) float  g_Zp[NSPLIT][NQ];                 // partial Z
__device__ int g_ctr[NQT];                                        // arrival counters

// ---------------- helpers ----------------
__device__ __forceinline__ uint32_t smem_u32(const void* p) {
    uint32_t a;
    asm("{ .reg .u64 t; cvta.to.shared.u64 t, %1; cvt.u32.u64 %0, t; }" : "=r"(a) : "l"(p));
    return a;
}
__device__ __forceinline__ float ex2(float x) {
    float y; asm("ex2.approx.f32 %0, %1;" : "=f"(y) : "f"(x)); return y;
}
__device__ __forceinline__ void ldsm4(uint32_t* r, uint32_t addr) {
    asm volatile("ldmatrix.sync.aligned.m8n8.x4.shared.b16 {%0,%1,%2,%3}, [%4];"
                 : "=r"(r[0]), "=r"(r[1]), "=r"(r[2]), "=r"(r[3]) : "r"(addr));
}
__device__ __forceinline__ void mma16816(float* d, const uint32_t* a, uint32_t b0, uint32_t b1) {
    asm volatile("mma.sync.aligned.m16n8k16.row.col.f32.f16.f16.f32 "
                 "{%0,%1,%2,%3}, {%4,%5,%6,%7}, {%8,%9}, {%0,%1,%2,%3};"
                 : "+f"(d[0]), "+f"(d[1]), "+f"(d[2]), "+f"(d[3])
                 : "r"(a[0]), "r"(a[1]), "r"(a[2]), "r"(a[3]), "r"(b0), "r"(b1));
}
__device__ __forceinline__ void mma16816h(uint32_t* d, const uint32_t* a, uint32_t b0, uint32_t b1) {
    asm volatile("mma.sync.aligned.m16n8k16.row.col.f16.f16.f16.f16 "
                 "{%0,%1}, {%2,%3,%4,%5}, {%6,%7}, {%0,%1};"
                 : "+r"(d[0]), "+r"(d[1])
                 : "r"(a[0]), "r"(a[1]), "r"(a[2]), "r"(a[3]), "r"(b0), "r"(b1));
}
__device__ __forceinline__ uint32_t packh(float hi, float lo) {
    uint32_t r; asm("cvt.rn.f16x2.f32 %0, %1, %2;" : "=r"(r) : "f"(hi), "f"(lo)); return r;
}
__device__ __forceinline__ void cp16(uint32_t saddr, const void* g) {
    asm volatile("cp.async.cg.shared.global [%0], [%1], 16;" :: "r"(saddr), "l"(g));
}
#define CP_COMMIT() asm volatile("cp.async.commit_group;" ::: "memory")
#define CP_WAIT0()  asm volatile("cp.async.wait_group 0;" ::: "memory")

// ---------------- prep kernels ----------------
__global__ void prep_q(const float* __restrict__ q) {
    int row = blockIdx.x * 8 + (threadIdx.x >> 5);
    int lane = threadIdx.x & 31;
    float4 v = ((const float4*)q)[(size_t)row * 32 + lane];
    float ss = v.x * v.x + v.y * v.y + v.z * v.z + v.w * v.w;
    #pragma unroll
    for (int o = 16; o > 0; o >>= 1) ss += __shfl_xor_sync(0xffffffffu, ss, o);
    float sc = 1.44269504f / fmaxf(sqrtf(ss), 1e-12f);   // fold log2(e)
    __half2* dst = (__half2*)(g_Qh + (size_t)row * DIM + lane * 4);
    dst[0] = __float22half2_rn(make_float2(v.x * sc, v.y * sc));
    dst[1] = __float22half2_rn(make_float2(v.z * sc, v.w * sc));
}

__global__ void prep_k(const float* __restrict__ keys) {
    if (threadIdx.x == 0) g_ctr[blockIdx.x] = 0;   // 512 blocks == NQT counters
    int row = blockIdx.x * 8 + (threadIdx.x >> 5);
    int lane = threadIdx.x & 31;
    float4 v = ((const float4*)keys)[(size_t)row * 32 + lane];
    float ss = v.x * v.x + v.y * v.y + v.z * v.z + v.w * v.w;
    #pragma unroll
    for (int o = 16; o > 0; o >>= 1) ss += __shfl_xor_sync(0xffffffffu, ss, o);
    float sc = 1.0f / fmaxf(sqrtf(ss), 1e-12f);
    __half2* dst = (__half2*)(g_Kh + (size_t)row * DIM + lane * 4);
    dst[0] = __float22half2_rn(make_float2(v.x * sc, v.y * sc));
    dst[1] = __float22half2_rn(make_float2(v.z * sc, v.w * sc));
    float xs[4] = {v.x, v.y, v.z, v.w};
    #pragma unroll
    for (int j = 0; j < 4; ++j)
        g_Vt[(size_t)(lane * 4 + j) * NKEY + row] = __float2half(xs[j]);
}

__global__ void prep_colsum(const float* __restrict__ keys) {
    __shared__ float red[256];
    int d = blockIdx.x;
    float s = 0.f;
    for (int k = threadIdx.x; k < NKEY; k += 256) s += keys[(size_t)k * DIM + d];
    red[threadIdx.x] = s;
    __syncthreads();
    for (int o = 128; o > 0; o >>= 1) {
        if ((int)threadIdx.x < o) red[threadIdx.x] += red[threadIdx.x + o];
        __syncthreads();
    }
    if (threadIdx.x == 0) g_colsum[d] = red[0];
}

// ---------------- main kernel ----------------
#define STG   35840
#define VOFF  17408
enum { FLAGOF = 2 * STG, SMTOT = 2 * STG + 512 };

__device__ __forceinline__ void issue_tile(uint32_t sb, int stg, int t, int tid) {
    uint32_t kb = sb + stg * STG;
    uint32_t vb = kb + VOFF;
    const __half* ks = g_Kh + (size_t)t * BK * DIM;
    const __half* vs = g_Vt + (size_t)t * BK;
    #pragma unroll
    for (int c = 0; c < 8; ++c) {
        int chunk = c * NTHREADS + tid;
        int r = chunk >> 4, o = chunk & 15;
        cp16(kb + r * SROWK + o * 16, ks + (size_t)r * DIM + o * 8);
    }
    #pragma unroll
    for (int c = 0; c < 8; ++c) {
        int chunk = c * NTHREADS + tid;
        int r = chunk >> 3, o = chunk & 7;
        cp16(vb + r * SROWV + o * 16, vs + (size_t)r * NKEY + o * 8);
    }
}

__global__ __launch_bounds__(NTHREADS, 2)
void mb_main(float* __restrict__ out) {
    extern __shared__ char sm[];
    const uint32_t sb = smem_u32(sm);
    const int tid = threadIdx.x, wid = tid >> 5, lane = tid & 31;
    const int qt = blockIdx.x >> 2;        // Q tile
    const int sp = blockIdx.x & 3;         // key split
    const int t0 = sp * TPS;

    // Stage this CTA's 128-row Q tile into stage-0 region.
    {
        const __half* qs = g_Qh + (size_t)qt * BM * DIM;
        #pragma unroll
        for (int c = 0; c < 16; ++c) {
            int chunk = c * NTHREADS + tid;
            int r = chunk >> 4, o = chunk & 15;
            *(uint4*)(sm + r * SROWK + o * 16) =
                *(const uint4*)(qs + (size_t)r * DIM + o * 8);
        }
    }
    __syncthreads();
    uint32_t qa[2][8][4];
    {
        int colh = (lane >> 4) * 8;
        #pragma unroll
        for (int rb = 0; rb < 2; ++rb) {
            int row = wid * 32 + rb * 16 + (lane & 15);
            #pragma unroll
            for (int k = 0; k < 8; ++k)
                ldsm4(qa[rb][k], sb + row * SROWK + (k * 16 + colh) * 2);
        }
    }
    __syncthreads();
    issue_tile(sb, 0, t0, tid); CP_COMMIT();

    float o_acc[2][16][4];
    #pragma unroll
    for (int rb = 0; rb < 2; ++rb)
        #pragma unroll
        for (int j = 0; j < 16; ++j)
            #pragma unroll
            for (int c = 0; c < 4; ++c) o_acc[rb][j][c] = 0.f;
    float zlo[2] = {0.f, 0.f}, zhi[2] = {0.f, 0.f};

    const int bg = (lane >> 3) & 1, bc = (lane >> 4), br = lane & 7;
    const int krow = bg * 8 + br;

    for (int i = 0; i < TPS; ++i) {
        int stg = i & 1;
        CP_WAIT0();
        __syncthreads();
        if (i + 1 < TPS) issue_tile(sb, stg ^ 1, t0 + i + 1, tid);
        CP_COMMIT();

        uint32_t kb = sb + stg * STG;
        uint32_t vb = kb + VOFF;

        #pragma unroll
        for (int s = 0; s < 4; ++s) {
            // ---- S: fp16-accum MMAs ----
            uint32_t d0[2][2] = {{0u,0u},{0u,0u}};
            uint32_t d1[2][2] = {{0u,0u},{0u,0u}};
            #pragma unroll
            for (int k = 0; k < 8; ++k) {
                uint32_t kf[4];
                ldsm4(kf, kb + (uint32_t)((s * 16 + krow) * SROWK + (k * 16 + bc * 8) * 2));
                mma16816h(d0[0], qa[0][k], kf[0], kf[2]);
                mma16816h(d1[0], qa[0][k], kf[1], kf[3]);
                mma16816h(d0[1], qa[1][k], kf[0], kf[2]);
                mma16816h(d1[1], qa[1][k], kf[1], kf[3]);
            }
            // ---- ex2(s)-1, Z partials, pack PV A-fragments ----
            uint32_t pa[2][4];
            #pragma unroll
            for (int rb = 0; rb < 2; ++rb) {
                float2 s01 = __half22float2(*(__half2*)&d0[rb][0]);
                float2 s23 = __half22float2(*(__half2*)&d0[rb][1]);
                float2 t01 = __half22float2(*(__half2*)&d1[rb][0]);
                float2 t23 = __half22float2(*(__half2*)&d1[rb][1]);
                float p00 = ex2(s01.x) - 1.f, p01 = ex2(s01.y) - 1.f;
                float p02 = ex2(s23.x) - 1.f, p03 = ex2(s23.y) - 1.f;
                float p10 = ex2(t01.x) - 1.f, p11 = ex2(t01.y) - 1.f;
                float p12 = ex2(t23.x) - 1.f, p13 = ex2(t23.y) - 1.f;
                zlo[rb] += (p00 + p01) + (p10 + p11);
                zhi[rb] += (p02 + p03) + (p12 + p13);
                pa[rb][0] = packh(p01, p00);
                pa[rb][1] = packh(p03, p02);
                pa[rb][2] = packh(p11, p10);
                pa[rb][3] = packh(p13, p12);
            }
            // ---- O += P @ V (fp32 accum) ----
            #pragma unroll
            for (int j = 0; j < 8; ++j) {
                uint32_t vf[4];
                ldsm4(vf, vb + (uint32_t)((j * 16 + krow) * SROWV + (s * 16 + bc * 8) * 2));
                mma16816(o_acc[0][2 * j],     pa[0], vf[0], vf[2]);
                mma16816(o_acc[0][2 * j + 1], pa[0], vf[1], vf[3]);
                mma16816(o_acc[1][2 * j],     pa[1], vf[0], vf[2]);
                mma16816(o_acc[1][2 * j + 1], pa[1], vf[1], vf[3]);
            }
        }
    }

    // ---- epilogue: write fp16 partials ----
    __half* op = g_OpH[sp];
    int col0 = (lane & 3) * 2;
    #pragma unroll
    for (int rb = 0; rb < 2; ++rb) {
        float zl = zlo[rb], zh = zhi[rb];
        zl += __shfl_xor_sync(0xffffffffu, zl, 1);
        zl += __shfl_xor_sync(0xffffffffu, zl, 2);
        zh += __shfl_xor_sync(0xffffffffu, zh, 1);
        zh += __shfl_xor_sync(0xffffffffu, zh, 2);
        size_t row0 = (size_t)qt * BM + wid * 32 + rb * 16 + (lane >> 2);
        if ((lane & 3) == 0) {
            g_Zp[sp][row0] = zl;
            g_Zp[sp][row0 + 8] = zh;
        }
        #pragma unroll
        for (int j = 0; j < 16; ++j) {
            int c = j * 8 + col0;
            *(__half2*)&op[row0 * DIM + c] =
                __floats2half2_rn(o_acc[rb][j][0], o_acc[rb][j][1]);
            *(__half2*)&op[(row0 + 8) * DIM + c] =
                __floats2half2_rn(o_acc[rb][j][2], o_acc[rb][j][3]);
        }
    }

    // ---- fused combine: last split CTA of this q-tile finishes the job ----
    __threadfence();            // partials visible before counter bump
    __syncthreads();
    if (tid == 0)
        *(int*)(sm + FLAGOF) = (atomicAdd(&g_ctr[qt], 1) == NSPLIT - 1);
    __syncthreads();
    if (*(int*)(sm + FLAGOF)) {
        __threadfence();        // other splits' partials acquired
        // warp w handles rows w*32..w*32+31; lane handles 4 cols.
        int cc = lane * 4;
        for (int rr = 0; rr < 32; ++rr) {
            size_t row = (size_t)qt * BM + wid * 32 + rr;
            float z = (float)NKEY + g_Zp[0][row] + g_Zp[1][row]
                    + g_Zp[2][row] + g_Zp[3][row];
            float inv = 1.0f / z;
            size_t off = row * DIM + cc;
            float acc0 = g_colsum[cc],     acc1 = g_colsum[cc + 1];
            float acc2 = g_colsum[cc + 2], acc3 = g_colsum[cc + 3];
            #pragma unroll
            for (int spp = 0; spp < NSPLIT; ++spp) {
                uint2 raw = *(const uint2*)&g_OpH[spp][off];
                float2 a = __half22float2(*(__half2*)&raw.x);
                float2 b = __half22float2(*(__half2*)&raw.y);
                acc0 += a.x; acc1 += a.y; acc2 += b.x; acc3 += b.y;
            }
            *(float4*)&out[off] =
                make_float4(acc0 * inv, acc1 * inv, acc2 * inv, acc3 * inv);
        }
    }
}

// ---------------- launch ----------------
extern "C" void kernel_launch(void* const* d_in, const int* in_sizes, int n_in,
                              void* d_out, int out_size) {
    const float* queries = (const float*)d_in[0];
    const float* keys    = (const float*)d_in[1];
    float* out = (float*)d_out;
    int N = in_sizes[0] / DIM;

    prep_q<<<N / 8, 256>>>(queries);
    prep_k<<<NKEY / 8, 256>>>(keys);      // also zeroes g_ctr (512 blocks)
    prep_colsum<<<DIM, 256>>>(keys);

    cudaFuncSetAttribute(mb_main, cudaFuncAttributeMaxDynamicSharedMemorySize, SMTOT);
    mb_main<<<(N / BM) * NSPLIT, NTHREADS, SMTOT>>>(out);
}

// round 17
// speedup vs baseline: 1.0795x; 1.0795x over previous
#include <cuda_runtime.h>
#include <cuda_fp16.h>
#include <cstdint>

// out = softmax(normalize(Q)@normalize(K)^T) @ K,  N=65536, K=4096, D=128, fp32
// fp16 mma.sync dataflow, split-K x4, fp16 partials + separate combine
// (R14 config, proven 437us / rel_err 1.12e-4).
// R16: single merged prep launch (Q-norm / K-norm+V^T / colsum by block range)
//      + wider (16B/split) combine loads. Mainloop untouched.

#define NQ 65536
#define NKEY 4096
#define DIM 128
#define BM 128            // 4 warps x 32 rows
#define BK 64
#define NSPLIT 4
#define TPS (NKEY / BK / NSPLIT)   // 16 tiles per split
#define NTHREADS 128
#define SROWK 272
#define SROWV 144

#define QBLK (NQ / 8)              // 8192 prep blocks for Q
#define KBLK (NKEY / 8)            // 512 prep blocks for K

__device__ __align__(16) __half g_Qh[(size_t)NQ * DIM];    // normalized Q * log2e
__device__ __align__(16) __half g_Kh[(size_t)NKEY * DIM];  // NORMALIZED keys
__device__ __align__(16) __half g_Vt[(size_t)DIM * NKEY];  // raw keys^T [d][key]
__device__ __align__(16) float  g_colsum[DIM];
__device__ __align__(16) __half g_OpH[NSPLIT][(size_t)NQ * DIM];  // fp16 partials
__device__ __align__(16) float  g_Zp[NSPLIT][NQ];                 // partial Z

// ---------------- helpers ----------------
__device__ __forceinline__ uint32_t smem_u32(const void* p) {
    uint32_t a;
    asm("{ .reg .u64 t; cvta.to.shared.u64 t, %1; cvt.u32.u64 %0, t; }" : "=r"(a) : "l"(p));
    return a;
}
__device__ __forceinline__ float ex2(float x) {
    float y; asm("ex2.approx.f32 %0, %1;" : "=f"(y) : "f"(x)); return y;
}
__device__ __forceinline__ void ldsm4(uint32_t* r, uint32_t addr) {
    asm volatile("ldmatrix.sync.aligned.m8n8.x4.shared.b16 {%0,%1,%2,%3}, [%4];"
                 : "=r"(r[0]), "=r"(r[1]), "=r"(r[2]), "=r"(r[3]) : "r"(addr));
}
__device__ __forceinline__ void mma16816(float* d, const uint32_t* a, uint32_t b0, uint32_t b1) {
    asm volatile("mma.sync.aligned.m16n8k16.row.col.f32.f16.f16.f32 "
                 "{%0,%1,%2,%3}, {%4,%5,%6,%7}, {%8,%9}, {%0,%1,%2,%3};"
                 : "+f"(d[0]), "+f"(d[1]), "+f"(d[2]), "+f"(d[3])
                 : "r"(a[0]), "r"(a[1]), "r"(a[2]), "r"(a[3]), "r"(b0), "r"(b1));
}
__device__ __forceinline__ void mma16816h(uint32_t* d, const uint32_t* a, uint32_t b0, uint32_t b1) {
    asm volatile("mma.sync.aligned.m16n8k16.row.col.f16.f16.f16.f16 "
                 "{%0,%1}, {%2,%3,%4,%5}, {%6,%7}, {%0,%1};"
                 : "+r"(d[0]), "+r"(d[1])
                 : "r"(a[0]), "r"(a[1]), "r"(a[2]), "r"(a[3]), "r"(b0), "r"(b1));
}
__device__ __forceinline__ uint32_t packh(float hi, float lo) {
    uint32_t r; asm("cvt.rn.f16x2.f32 %0, %1, %2;" : "=r"(r) : "f"(hi), "f"(lo)); return r;
}
__device__ __forceinline__ void cp16(uint32_t saddr, const void* g) {
    asm volatile("cp.async.cg.shared.global [%0], [%1], 16;" :: "r"(saddr), "l"(g));
}
#define CP_COMMIT() asm volatile("cp.async.commit_group;" ::: "memory")
#define CP_WAIT0()  asm volatile("cp.async.wait_group 0;" ::: "memory")

// ---------------- merged prep kernel ----------------
// blocks [0, QBLK)               : normalize Q (8 rows/block)
// blocks [QBLK, QBLK+KBLK)       : normalize K + build V^T (8 rows/block)
// blocks [QBLK+KBLK, +DIM)       : exact fp32 column sums of V (1 col/block)
__global__ void prep_all(const float* __restrict__ q, const float* __restrict__ keys) {
    __shared__ float red[256];
    int b = blockIdx.x;
    if (b < QBLK) {
        int row = b * 8 + (threadIdx.x >> 5);
        int lane = threadIdx.x & 31;
        float4 v = ((const float4*)q)[(size_t)row * 32 + lane];
        float ss = v.x * v.x + v.y * v.y + v.z * v.z + v.w * v.w;
        #pragma unroll
        for (int o = 16; o > 0; o >>= 1) ss += __shfl_xor_sync(0xffffffffu, ss, o);
        float sc = 1.44269504f / fmaxf(sqrtf(ss), 1e-12f);   // fold log2(e)
        __half2* dst = (__half2*)(g_Qh + (size_t)row * DIM + lane * 4);
        dst[0] = __float22half2_rn(make_float2(v.x * sc, v.y * sc));
        dst[1] = __float22half2_rn(make_float2(v.z * sc, v.w * sc));
    } else if (b < QBLK + KBLK) {
        int row = (b - QBLK) * 8 + (threadIdx.x >> 5);
        int lane = threadIdx.x & 31;
        float4 v = ((const float4*)keys)[(size_t)row * 32 + lane];
        float ss = v.x * v.x + v.y * v.y + v.z * v.z + v.w * v.w;
        #pragma unroll
        for (int o = 16; o > 0; o >>= 1) ss += __shfl_xor_sync(0xffffffffu, ss, o);
        float sc = 1.0f / fmaxf(sqrtf(ss), 1e-12f);
        __half2* dst = (__half2*)(g_Kh + (size_t)row * DIM + lane * 4);
        dst[0] = __float22half2_rn(make_float2(v.x * sc, v.y * sc));
        dst[1] = __float22half2_rn(make_float2(v.z * sc, v.w * sc));
        float xs[4] = {v.x, v.y, v.z, v.w};
        #pragma unroll
        for (int j = 0; j < 4; ++j)
            g_Vt[(size_t)(lane * 4 + j) * NKEY + row] = __float2half(xs[j]);
    } else {
        int d = b - (QBLK + KBLK);
        float s = 0.f;
        for (int k = threadIdx.x; k < NKEY; k += 256) s += keys[(size_t)k * DIM + d];
        red[threadIdx.x] = s;
        __syncthreads();
        for (int o = 128; o > 0; o >>= 1) {
            if ((int)threadIdx.x < o) red[threadIdx.x] += red[threadIdx.x + o];
            __syncthreads();
        }
        if (threadIdx.x == 0) g_colsum[d] = red[0];
    }
}

// ---------------- main kernel ----------------
#define STG   35840
#define VOFF  17408
enum { SMTOT = 2 * STG + 512 };

__device__ __forceinline__ void issue_tile(uint32_t sb, int stg, int t, int tid) {
    uint32_t kb = sb + stg * STG;
    uint32_t vb = kb + VOFF;
    const __half* ks = g_Kh + (size_t)t * BK * DIM;
    const __half* vs = g_Vt + (size_t)t * BK;
    #pragma unroll
    for (int c = 0; c < 8; ++c) {
        int chunk = c * NTHREADS + tid;
        int r = chunk >> 4, o = chunk & 15;
        cp16(kb + r * SROWK + o * 16, ks + (size_t)r * DIM + o * 8);
    }
    #pragma unroll
    for (int c = 0; c < 8; ++c) {
        int chunk = c * NTHREADS + tid;
        int r = chunk >> 3, o = chunk & 7;
        cp16(vb + r * SROWV + o * 16, vs + (size_t)r * NKEY + o * 8);
    }
}

__global__ __launch_bounds__(NTHREADS, 2)
void mb_main() {
    extern __shared__ char sm[];
    const uint32_t sb = smem_u32(sm);
    const int tid = threadIdx.x, wid = tid >> 5, lane = tid & 31;
    const int qt = blockIdx.x >> 2;        // Q tile
    const int sp = blockIdx.x & 3;         // key split
    const int t0 = sp * TPS;

    // Stage this CTA's 128-row Q tile into stage-0 region.
    {
        const __half* qs = g_Qh + (size_t)qt * BM * DIM;
        #pragma unroll
        for (int c = 0; c < 16; ++c) {
            int chunk = c * NTHREADS + tid;
            int r = chunk >> 4, o = chunk & 15;
            *(uint4*)(sm + r * SROWK + o * 16) =
                *(const uint4*)(qs + (size_t)r * DIM + o * 8);
        }
    }
    __syncthreads();
    uint32_t qa[2][8][4];
    {
        int colh = (lane >> 4) * 8;
        #pragma unroll
        for (int rb = 0; rb < 2; ++rb) {
            int row = wid * 32 + rb * 16 + (lane & 15);
            #pragma unroll
            for (int k = 0; k < 8; ++k)
                ldsm4(qa[rb][k], sb + row * SROWK + (k * 16 + colh) * 2);
        }
    }
    __syncthreads();
    issue_tile(sb, 0, t0, tid); CP_COMMIT();

    float o_acc[2][16][4];
    #pragma unroll
    for (int rb = 0; rb < 2; ++rb)
        #pragma unroll
        for (int j = 0; j < 16; ++j)
            #pragma unroll
            for (int c = 0; c < 4; ++c) o_acc[rb][j][c] = 0.f;
    float zlo[2] = {0.f, 0.f}, zhi[2] = {0.f, 0.f};

    const int bg = (lane >> 3) & 1, bc = (lane >> 4), br = lane & 7;
    const int krow = bg * 8 + br;

    for (int i = 0; i < TPS; ++i) {
        int stg = i & 1;
        CP_WAIT0();
        __syncthreads();
        if (i + 1 < TPS) issue_tile(sb, stg ^ 1, t0 + i + 1, tid);
        CP_COMMIT();

        uint32_t kb = sb + stg * STG;
        uint32_t vb = kb + VOFF;

        #pragma unroll
        for (int s = 0; s < 4; ++s) {
            // ---- S: fp16-accum MMAs ----
            uint32_t d0[2][2] = {{0u,0u},{0u,0u}};
            uint32_t d1[2][2] = {{0u,0u},{0u,0u}};
            #pragma unroll
            for (int k = 0; k < 8; ++k) {
                uint32_t kf[4];
                ldsm4(kf, kb + (uint32_t)((s * 16 + krow) * SROWK + (k * 16 + bc * 8) * 2));
                mma16816h(d0[0], qa[0][k], kf[0], kf[2]);
                mma16816h(d1[0], qa[0][k], kf[1], kf[3]);
                mma16816h(d0[1], qa[1][k], kf[0], kf[2]);
                mma16816h(d1[1], qa[1][k], kf[1], kf[3]);
            }
            // ---- ex2(s)-1, Z partials, pack PV A-fragments ----
            uint32_t pa[2][4];
            #pragma unroll
            for (int rb = 0; rb < 2; ++rb) {
                float2 s01 = __half22float2(*(__half2*)&d0[rb][0]);
                float2 s23 = __half22float2(*(__half2*)&d0[rb][1]);
                float2 t01 = __half22float2(*(__half2*)&d1[rb][0]);
                float2 t23 = __half22float2(*(__half2*)&d1[rb][1]);
                float p00 = ex2(s01.x) - 1.f, p01 = ex2(s01.y) - 1.f;
                float p02 = ex2(s23.x) - 1.f, p03 = ex2(s23.y) - 1.f;
                float p10 = ex2(t01.x) - 1.f, p11 = ex2(t01.y) - 1.f;
                float p12 = ex2(t23.x) - 1.f, p13 = ex2(t23.y) - 1.f;
                zlo[rb] += (p00 + p01) + (p10 + p11);
                zhi[rb] += (p02 + p03) + (p12 + p13);
                pa[rb][0] = packh(p01, p00);
                pa[rb][1] = packh(p03, p02);
                pa[rb][2] = packh(p11, p10);
                pa[rb][3] = packh(p13, p12);
            }
            // ---- O += P @ V (fp32 accum) ----
            #pragma unroll
            for (int j = 0; j < 8; ++j) {
                uint32_t vf[4];
                ldsm4(vf, vb + (uint32_t)((j * 16 + krow) * SROWV + (s * 16 + bc * 8) * 2));
                mma16816(o_acc[0][2 * j],     pa[0], vf[0], vf[2]);
                mma16816(o_acc[0][2 * j + 1], pa[0], vf[1], vf[3]);
                mma16816(o_acc[1][2 * j],     pa[1], vf[0], vf[2]);
                mma16816(o_acc[1][2 * j + 1], pa[1], vf[1], vf[3]);
            }
        }
    }

    // ---- epilogue: write fp16 partials ----
    __half* op = g_OpH[sp];
    int col0 = (lane & 3) * 2;
    #pragma unroll
    for (int rb = 0; rb < 2; ++rb) {
        float zl = zlo[rb], zh = zhi[rb];
        zl += __shfl_xor_sync(0xffffffffu, zl, 1);
        zl += __shfl_xor_sync(0xffffffffu, zl, 2);
        zh += __shfl_xor_sync(0xffffffffu, zh, 1);
        zh += __shfl_xor_sync(0xffffffffu, zh, 2);
        size_t row0 = (size_t)qt * BM + wid * 32 + rb * 16 + (lane >> 2);
        if ((lane & 3) == 0) {
            g_Zp[sp][row0] = zl;
            g_Zp[sp][row0 + 8] = zh;
        }
        #pragma unroll
        for (int j = 0; j < 16; ++j) {
            int c = j * 8 + col0;
            *(__half2*)&op[row0 * DIM + c] =
                __floats2half2_rn(o_acc[rb][j][0], o_acc[rb][j][1]);
            *(__half2*)&op[(row0 + 8) * DIM + c] =
                __floats2half2_rn(o_acc[rb][j][2], o_acc[rb][j][3]);
        }
    }
}

// ---------------- combine kernel (wide loads: 16B per split per thread) ----
__global__ void mb_combine(float* __restrict__ out) {
    // grid 4096 x 256 threads; block = 16 rows, thread = 8 cols.
    int r = blockIdx.x * 16 + (threadIdx.x >> 4);
    int c = (threadIdx.x & 15) * 8;
    float z = (float)NKEY + g_Zp[0][r] + g_Zp[1][r] + g_Zp[2][r] + g_Zp[3][r];
    float inv = 1.0f / z;
    size_t off = (size_t)r * DIM + c;
    float acc[8];
    #pragma unroll
    for (int j = 0; j < 8; ++j) acc[j] = g_colsum[c + j];
    #pragma unroll
    for (int sp = 0; sp < NSPLIT; ++sp) {
        uint4 raw = *(const uint4*)&g_OpH[sp][off];
        float2 a = __half22float2(*(__half2*)&raw.x);
        float2 b = __half22float2(*(__half2*)&raw.y);
        float2 cc = __half22float2(*(__half2*)&raw.z);
        float2 d = __half22float2(*(__half2*)&raw.w);
        acc[0] += a.x;  acc[1] += a.y;  acc[2] += b.x;  acc[3] += b.y;
        acc[4] += cc.x; acc[5] += cc.y; acc[6] += d.x;  acc[7] += d.y;
    }
    float4 o0 = make_float4(acc[0] * inv, acc[1] * inv, acc[2] * inv, acc[3] * inv);
    float4 o1 = make_float4(acc[4] * inv, acc[5] * inv, acc[6] * inv, acc[7] * inv);
    *(float4*)&out[off] = o0;
    *(float4*)&out[off + 4] = o1;
}

// ---------------- launch ----------------
extern "C" void kernel_launch(void* const* d_in, const int* in_sizes, int n_in,
                              void* d_out, int out_size) {
    const float* queries = (const float*)d_in[0];
    const float* keys    = (const float*)d_in[1];
    float* out = (float*)d_out;
    int N = in_sizes[0] / DIM;

    prep_all<<<QBLK + KBLK + DIM, 256>>>(queries, keys);

    cudaFuncSetAttribute(mb_main, cudaFuncAttributeMaxDynamicSharedMemorySize, SMTOT);
    mb_main<<<(N / BM) * NSPLIT, NTHREADS, SMTOT>>>();
    mb_combine<<<N / 16, 256>>>(out);
}